// round 3
// baseline (speedup 1.0000x reference)
#include <cuda_runtime.h>
#include <cuda_bf16.h>
#include <cstdint>

// ---------------------------------------------------------------------------
// GCN 2-layer forward:  x[N,3] -> GCNConv(3,16)+ReLU -> GCNConv(16,7) -> log_softmax
// N = 500000, E = 16e6. Symmetric norm D^-1/2 (A+I) D^-1/2, self-loops folded
// into the per-node init kernels (no self-loop edges processed).
//
// edge_index dtype is detected at runtime (int64 vs int32 staging) via a
// device-side flag; all edge kernels branch uniformly on it and predicate
// out-of-range indices (crash-proofing).
// ---------------------------------------------------------------------------

#define NMAX 500000
#define F1   16        // hidden dim
#define F2   7         // out dim
#define F2P  8         // padded stride for vector atomics

__device__ __align__(16) int   g_deg [NMAX];
__device__ __align__(16) float g_dinv[NMAX];
__device__ __align__(16) float g_xw  [(size_t)NMAX * F1];   // x @ W1 per node
__device__ __align__(16) float g_h1  [(size_t)NMAX * F1];   // layer-1 accumulator
__device__ __align__(16) float g_hw2 [(size_t)NMAX * F2P];  // relu(h1)@W2 (padded)
__device__ __align__(16) float g_acc2[(size_t)NMAX * F2P];  // layer-2 accumulator (padded)
__device__ int g_is64;                                      // 1 if edge_index is int64

// ---- vector reduction helper (sm_90+) -------------------------------------
__device__ __forceinline__ void red_add_v4(float* addr, float4 v) {
    asm volatile("red.global.add.v4.f32 [%0], {%1, %2, %3, %4};"
                 :: "l"(addr), "f"(v.x), "f"(v.y), "f"(v.z), "f"(v.w)
                 : "memory");
}

// ---- edge index fetch (dtype-flexible, range-guarded) ----------------------
__device__ __forceinline__ bool load_edge(const void* ei, int e, int i, int n,
                                          int is64, int& s, int& d) {
    if (is64) {
        const long long* p = (const long long*)ei;
        long long sv = __ldg(&p[i]);
        long long dv = __ldg(&p[(size_t)e + i]);
        s = (int)sv; d = (int)dv;
        return (sv >= 0 && sv < n && dv >= 0 && dv < n);
    } else {
        const int* p = (const int*)ei;
        s = __ldg(&p[i]);
        d = __ldg(&p[(size_t)e + i]);
        return (s >= 0 && s < n && d >= 0 && d < n);
    }
}

// ---- K-1: detect edge_index dtype -----------------------------------------
__global__ void k_detect(const void* ei, int e, int n) {
    if (blockIdx.x != 0 || threadIdx.x != 0) return;
    const long long* p = (const long long*)ei;
    int ok = 1;
    int step = e / 64;
    if (step < 1) step = 1;
    for (int k = 0; k < 64; k++) {
        long long v = p[(size_t)k * step];
        if (v < 0 || v >= n) { ok = 0; break; }
    }
    g_is64 = ok;
}

// ---- K0: zero degree ------------------------------------------------------
__global__ void k_zero_deg(int n) {
    int i = blockIdx.x * blockDim.x + threadIdx.x;
    if (i < n) g_deg[i] = 0;
}

// ---- K1: in-degree count --------------------------------------------------
__global__ void k_degree(const void* __restrict__ ei, int e, int n) {
    int i = blockIdx.x * blockDim.x + threadIdx.x;
    if (i >= e) return;
    int is64 = g_is64;
    int s, d;
    if (load_edge(ei, e, i, n, is64, s, d))
        atomicAdd(&g_deg[d], 1);
}

// ---- K2: dinv, xW1, h1 init with self-loop contribution -------------------
__global__ void k_node1(const float* __restrict__ x,
                        const float* __restrict__ W1, int n) {
    int i = blockIdx.x * blockDim.x + threadIdx.x;
    if (i >= n) return;
    float di = rsqrtf((float)(g_deg[i] + 1));   // deg includes self loop
    g_dinv[i] = di;
    float self = di * di;
    float x0 = __ldg(&x[3*i+0]), x1 = __ldg(&x[3*i+1]), x2 = __ldg(&x[3*i+2]);
    size_t base = (size_t)i * F1;
    #pragma unroll
    for (int j = 0; j < F1; j++) {
        float w = x0 * __ldg(&W1[j]) + x1 * __ldg(&W1[F1 + j]) + x2 * __ldg(&W1[2*F1 + j]);
        g_xw[base + j] = w;
        g_h1[base + j] = self * w;
    }
}

// ---- K3: layer-1 edge scatter ---------------------------------------------
__global__ void k_edge1(const void* __restrict__ ei, int e, int n) {
    int i = blockIdx.x * blockDim.x + threadIdx.x;
    if (i >= e) return;
    int is64 = g_is64;
    int s, d;
    if (!load_edge(ei, e, i, n, is64, s, d)) return;
    float nm = __ldg(&g_dinv[s]) * __ldg(&g_dinv[d]);
    const float4* xs = (const float4*)(g_xw + (size_t)s * F1);
    float*        hd = g_h1 + (size_t)d * F1;
    float4 v0 = __ldg(&xs[0]), v1 = __ldg(&xs[1]), v2 = __ldg(&xs[2]), v3 = __ldg(&xs[3]);
    v0.x*=nm; v0.y*=nm; v0.z*=nm; v0.w*=nm;
    v1.x*=nm; v1.y*=nm; v1.z*=nm; v1.w*=nm;
    v2.x*=nm; v2.y*=nm; v2.z*=nm; v2.w*=nm;
    v3.x*=nm; v3.y*=nm; v3.z*=nm; v3.w*=nm;
    red_add_v4(hd + 0,  v0);
    red_add_v4(hd + 4,  v1);
    red_add_v4(hd + 8,  v2);
    red_add_v4(hd + 12, v3);
}

// ---- K4: ReLU(+b1), hW2, acc2 init with self-loop -------------------------
__global__ void k_node2(const float* __restrict__ b1,
                        const float* __restrict__ W2, int n) {
    int i = blockIdx.x * blockDim.x + threadIdx.x;
    if (i >= n) return;
    size_t base = (size_t)i * F1;
    float h[F1];
    #pragma unroll
    for (int k = 0; k < F1; k++)
        h[k] = fmaxf(g_h1[base + k] + __ldg(&b1[k]), 0.0f);
    float di = g_dinv[i];
    float self = di * di;
    size_t ob = (size_t)i * F2P;
    #pragma unroll
    for (int j = 0; j < F2; j++) {
        float acc = 0.0f;
        #pragma unroll
        for (int k = 0; k < F1; k++)
            acc += h[k] * __ldg(&W2[k * F2 + j]);
        g_hw2 [ob + j] = acc;
        g_acc2[ob + j] = self * acc;
    }
    g_hw2 [ob + F2] = 0.0f;   // pad
    g_acc2[ob + F2] = 0.0f;   // pad
}

// ---- K5: layer-2 edge scatter ---------------------------------------------
__global__ void k_edge2(const void* __restrict__ ei, int e, int n) {
    int i = blockIdx.x * blockDim.x + threadIdx.x;
    if (i >= e) return;
    int is64 = g_is64;
    int s, d;
    if (!load_edge(ei, e, i, n, is64, s, d)) return;
    float nm = __ldg(&g_dinv[s]) * __ldg(&g_dinv[d]);
    const float4* xs = (const float4*)(g_hw2 + (size_t)s * F2P);
    float*        ad = g_acc2 + (size_t)d * F2P;
    float4 v0 = __ldg(&xs[0]), v1 = __ldg(&xs[1]);
    v0.x*=nm; v0.y*=nm; v0.z*=nm; v0.w*=nm;
    v1.x*=nm; v1.y*=nm; v1.z*=nm; v1.w*=nm;
    red_add_v4(ad + 0, v0);
    red_add_v4(ad + 4, v1);
}

// ---- K6: +b2, log_softmax, write output -----------------------------------
__global__ void k_out(const float* __restrict__ b2, float* __restrict__ out, int n) {
    int i = blockIdx.x * blockDim.x + threadIdx.x;
    if (i >= n) return;
    size_t ob = (size_t)i * F2P;
    float v[F2];
    float m = -1e30f;
    #pragma unroll
    for (int j = 0; j < F2; j++) {
        v[j] = g_acc2[ob + j] + __ldg(&b2[j]);
        m = fmaxf(m, v[j]);
    }
    float sum = 0.0f;
    #pragma unroll
    for (int j = 0; j < F2; j++) sum += __expf(v[j] - m);
    float lse = m + __logf(sum);
    #pragma unroll
    for (int j = 0; j < F2; j++) out[(size_t)i * F2 + j] = v[j] - lse;
}

// ---------------------------------------------------------------------------
extern "C" void kernel_launch(void* const* d_in, const int* in_sizes, int n_in,
                              void* d_out, int out_size) {
    const float* x  = (const float*)d_in[0];
    const void*  ei = d_in[1];                 // [2, E] int64 OR int32 (detected)
    const float* W1 = (const float*)d_in[2];
    const float* b1 = (const float*)d_in[3];
    const float* W2 = (const float*)d_in[4];
    const float* b2 = (const float*)d_in[5];
    float*       out = (float*)d_out;

    const int n = in_sizes[0] / 3;
    const int e = in_sizes[1] / 2;

    const int BT = 256;
    const int nb_n = (n + BT - 1) / BT;
    const int nb_e = (e + BT - 1) / BT;

    k_detect  <<<1, 32>>>(ei, e, n);
    k_zero_deg<<<nb_n, BT>>>(n);
    k_degree  <<<nb_e, BT>>>(ei, e, n);
    k_node1   <<<nb_n, BT>>>(x, W1, n);
    k_edge1   <<<nb_e, BT>>>(ei, e, n);
    k_node2   <<<nb_n, BT>>>(b1, W2, n);
    k_edge2   <<<nb_e, BT>>>(ei, e, n);
    k_out     <<<nb_n, BT>>>(b2, out, n);
}

// round 6
// speedup vs baseline: 1.3473x; 1.3473x over previous
#include <cuda_runtime.h>
#include <cuda_bf16.h>
#include <cstdint>

// ---------------------------------------------------------------------------
// GCN 2-layer forward. N=500000, E=16e6.  (R3-proven skeleton + norm folding)
//   g_xw[i]  = dinv[i] * (x[i] @ W1)        -> edge kernels are pure gather+red
//   acc1[d] += g_xw[s] over in-edges; init acc1[i] = g_xw[i] (self loop)
//   h[i]     = relu(dinv[i]*acc1[i] + b1)
//   g_hw2[i] = dinv[i] * (h[i] @ W2)
//   acc2[d] += g_hw2[s]; init acc2[i] = g_hw2[i]
//   out      = log_softmax(dinv[i]*acc2[i] + b2)
// edge_index dtype detected at runtime (int64 vs int32); guarded loads.
// ---------------------------------------------------------------------------

#define NMAX 500000
#define F1   16
#define F2   7
#define F2P  8

__device__ __align__(16) int   g_deg [NMAX];
__device__ __align__(16) float g_dinv[NMAX];
__device__ __align__(16) float g_xw  [(size_t)NMAX * F1];
__device__ __align__(16) float g_h1  [(size_t)NMAX * F1];
__device__ __align__(16) float g_hw2 [(size_t)NMAX * F2P];
__device__ __align__(16) float g_acc2[(size_t)NMAX * F2P];
__device__ int g_is64;

__device__ __forceinline__ void red_add_v4(float* addr, float4 v) {
    asm volatile("red.global.add.v4.f32 [%0], {%1, %2, %3, %4};"
                 :: "l"(addr), "f"(v.x), "f"(v.y), "f"(v.z), "f"(v.w)
                 : "memory");
}

// ---- edge index fetch (dtype-flexible, range-guarded) ----------------------
__device__ __forceinline__ bool load_edge(const void* ei, int e, int i, int n,
                                          int is64, int& s, int& d) {
    if (is64) {
        const long long* p = (const long long*)ei;
        long long sv = __ldg(&p[i]);
        long long dv = __ldg(&p[(size_t)e + i]);
        s = (int)sv; d = (int)dv;
        return (sv >= 0 && sv < n && dv >= 0 && dv < n);
    } else {
        const int* p = (const int*)ei;
        s = __ldg(&p[i]);
        d = __ldg(&p[(size_t)e + i]);
        return (s >= 0 && s < n && d >= 0 && d < n);
    }
}

// ---- K-1: detect edge_index dtype -----------------------------------------
__global__ void k_detect(const void* ei, int e, int n) {
    if (blockIdx.x != 0 || threadIdx.x != 0) return;
    const long long* p = (const long long*)ei;
    int ok = 1;
    int step = e / 64;
    if (step < 1) step = 1;
    for (int k = 0; k < 64; k++) {
        long long v = p[(size_t)k * step];
        if (v < 0 || v >= n) { ok = 0; break; }
    }
    g_is64 = ok;
}

// ---- K0: zero degree ------------------------------------------------------
__global__ void k_zero_deg(int n) {
    int i = blockIdx.x * blockDim.x + threadIdx.x;
    if (i < n) g_deg[i] = 0;
}

// ---- K1: in-degree count --------------------------------------------------
__global__ void k_degree(const void* __restrict__ ei, int e, int n) {
    int i = blockIdx.x * blockDim.x + threadIdx.x;
    if (i >= e) return;
    int is64 = g_is64;
    int s, d;
    if (load_edge(ei, e, i, n, is64, s, d))
        atomicAdd(&g_deg[d], 1);
}

// ---- K2: dinv, scaled xW1, acc1 init (float4 stores) ----------------------
__global__ void k_node1(const float* __restrict__ x,
                        const float* __restrict__ W1, int n) {
    int i = blockIdx.x * blockDim.x + threadIdx.x;
    if (i >= n) return;
    float di = rsqrtf((float)(g_deg[i] + 1));
    g_dinv[i] = di;
    float x0 = __ldg(&x[3*i+0]), x1 = __ldg(&x[3*i+1]), x2 = __ldg(&x[3*i+2]);
    float4* xw4 = (float4*)(g_xw + (size_t)i * F1);
    float4* h14 = (float4*)(g_h1 + (size_t)i * F1);
    #pragma unroll
    for (int q = 0; q < 4; q++) {
        float4 v;
        float* vp = (float*)&v;
        #pragma unroll
        for (int r = 0; r < 4; r++) {
            int j = q * 4 + r;
            vp[r] = di * (x0 * __ldg(&W1[j]) + x1 * __ldg(&W1[F1 + j])
                        + x2 * __ldg(&W1[2*F1 + j]));
        }
        xw4[q] = v;
        h14[q] = v;   // accumulator init = self-loop term (dst scale applied later)
    }
}

// ---- K3: layer-1 edge scatter (pure gather + reduce) ----------------------
__global__ void k_edge1(const void* __restrict__ ei, int e, int n) {
    int i = blockIdx.x * blockDim.x + threadIdx.x;
    if (i >= e) return;
    int is64 = g_is64;
    int s, d;
    if (!load_edge(ei, e, i, n, is64, s, d)) return;
    const float4* xs = (const float4*)(g_xw + (size_t)s * F1);
    float*        hd = g_h1 + (size_t)d * F1;
    red_add_v4(hd + 0,  __ldg(&xs[0]));
    red_add_v4(hd + 4,  __ldg(&xs[1]));
    red_add_v4(hd + 8,  __ldg(&xs[2]));
    red_add_v4(hd + 12, __ldg(&xs[3]));
}

// ---- K4: finish layer 1 (dinv, +b1, ReLU), build scaled hW2 ---------------
__global__ void k_node2(const float* __restrict__ b1,
                        const float* __restrict__ W2, int n) {
    int i = blockIdx.x * blockDim.x + threadIdx.x;
    if (i >= n) return;
    float di = g_dinv[i];
    size_t base = (size_t)i * F1;
    float h[F1];
    #pragma unroll
    for (int k = 0; k < F1; k++)
        h[k] = fmaxf(di * g_h1[base + k] + __ldg(&b1[k]), 0.0f);
    size_t ob = (size_t)i * F2P;
    float v[F2P];
    #pragma unroll
    for (int j = 0; j < F2; j++) {
        float acc = 0.0f;
        #pragma unroll
        for (int k = 0; k < F1; k++)
            acc += h[k] * __ldg(&W2[k * F2 + j]);
        v[j] = di * acc;
    }
    v[F2] = 0.0f;
    float4 p0 = make_float4(v[0], v[1], v[2], v[3]);
    float4 p1 = make_float4(v[4], v[5], v[6], v[7]);
    ((float4*)(g_hw2  + ob))[0] = p0;
    ((float4*)(g_hw2  + ob))[1] = p1;
    ((float4*)(g_acc2 + ob))[0] = p0;   // accumulator init = self-loop term
    ((float4*)(g_acc2 + ob))[1] = p1;
}

// ---- K5: layer-2 edge scatter ---------------------------------------------
__global__ void k_edge2(const void* __restrict__ ei, int e, int n) {
    int i = blockIdx.x * blockDim.x + threadIdx.x;
    if (i >= e) return;
    int is64 = g_is64;
    int s, d;
    if (!load_edge(ei, e, i, n, is64, s, d)) return;
    const float4* xs = (const float4*)(g_hw2 + (size_t)s * F2P);
    float*        ad = g_acc2 + (size_t)d * F2P;
    red_add_v4(ad + 0, __ldg(&xs[0]));
    red_add_v4(ad + 4, __ldg(&xs[1]));
}

// ---- K6: apply dinv, +b2, log_softmax -------------------------------------
__global__ void k_out(const float* __restrict__ b2, float* __restrict__ out, int n) {
    int i = blockIdx.x * blockDim.x + threadIdx.x;
    if (i >= n) return;
    float di = g_dinv[i];
    size_t ob = (size_t)i * F2P;
    float v[F2];
    float m = -1e30f;
    #pragma unroll
    for (int j = 0; j < F2; j++) {
        v[j] = di * g_acc2[ob + j] + __ldg(&b2[j]);
        m = fmaxf(m, v[j]);
    }
    float sum = 0.0f;
    #pragma unroll
    for (int j = 0; j < F2; j++) sum += __expf(v[j] - m);
    float lse = m + __logf(sum);
    #pragma unroll
    for (int j = 0; j < F2; j++) out[(size_t)i * F2 + j] = v[j] - lse;
}

// ---------------------------------------------------------------------------
extern "C" void kernel_launch(void* const* d_in, const int* in_sizes, int n_in,
                              void* d_out, int out_size) {
    const float* x  = (const float*)d_in[0];
    const void*  ei = d_in[1];                 // [2, E] int64 OR int32 (detected)
    const float* W1 = (const float*)d_in[2];
    const float* b1 = (const float*)d_in[3];
    const float* W2 = (const float*)d_in[4];
    const float* b2 = (const float*)d_in[5];
    float*       out = (float*)d_out;

    const int n = in_sizes[0] / 3;
    const int e = in_sizes[1] / 2;

    const int BT = 256;
    const int nb_n = (n + BT - 1) / BT;
    const int nb_e = (e + BT - 1) / BT;

    k_detect  <<<1, 32>>>(ei, e, n);
    k_zero_deg<<<nb_n, BT>>>(n);
    k_degree  <<<nb_e, BT>>>(ei, e, n);
    k_node1   <<<nb_n, BT>>>(x, W1, n);
    k_edge1   <<<nb_e, BT>>>(ei, e, n);
    k_node2   <<<nb_n, BT>>>(b1, W2, n);
    k_edge2   <<<nb_e, BT>>>(ei, e, n);
    k_out     <<<nb_n, BT>>>(b2, out, n);
}

// round 8
// speedup vs baseline: 2.2791x; 1.6916x over previous
#include <cuda_runtime.h>
#include <cuda_bf16.h>
#include <cstdint>

// ---------------------------------------------------------------------------
// GCN 2-layer forward. N=500000, E=16e6.
// Rank-3 trick: layer-1 aggregation is done on the RAW scaled features
// (3 floats, padded to 4), and the 3->16 GEMM happens per-node afterwards:
//   g_x4[i]  = dinv_i * (x_i, 0)              [float4]
//   a1[d]   += g_x4[s] over in-edges; init a1[i] = g_x4[i]  (self loop)
//   h[i]     = relu( (dinv_i * a1[i]) @ W1 + b1 )
//   g_hw2[i] = dinv_i * (h[i] @ W2)           [8 floats, 7 used]
//   acc2[d] += g_hw2[s]; init acc2[i] = g_hw2[i]
//   out      = log_softmax(dinv_i*acc2[i] + b2)
// Edge kernels: pure gather+reduce. edge1 = 1 LDG.128 + 1 RED.128 per edge.
// ---------------------------------------------------------------------------

#define NMAX 500000
#define F1   16
#define F2   7
#define F2P  8

__device__ __align__(16) int   g_deg [NMAX];
__device__ __align__(16) float g_dinv[NMAX];
__device__ __align__(16) float g_x4  [(size_t)NMAX * 4];   // dinv*x padded
__device__ __align__(16) float g_a1  [(size_t)NMAX * 4];   // layer-1 accumulator
__device__ __align__(16) float g_hw2 [(size_t)NMAX * F2P];
__device__ __align__(16) float g_acc2[(size_t)NMAX * F2P];
__device__ int g_is64;

__device__ __forceinline__ void red_add_v4(float* addr, float4 v) {
    asm volatile("red.global.add.v4.f32 [%0], {%1, %2, %3, %4};"
                 :: "l"(addr), "f"(v.x), "f"(v.y), "f"(v.z), "f"(v.w)
                 : "memory");
}

// ---- edge index fetch (dtype-flexible, range-guarded) ----------------------
__device__ __forceinline__ bool load_edge(const void* ei, int e, int i, int n,
                                          int is64, int& s, int& d) {
    if (is64) {
        const long long* p = (const long long*)ei;
        long long sv = __ldg(&p[i]);
        long long dv = __ldg(&p[(size_t)e + i]);
        s = (int)sv; d = (int)dv;
        return (sv >= 0 && sv < n && dv >= 0 && dv < n);
    } else {
        const int* p = (const int*)ei;
        s = __ldg(&p[i]);
        d = __ldg(&p[(size_t)e + i]);
        return (s >= 0 && s < n && d >= 0 && d < n);
    }
}

// ---- K-1: detect edge_index dtype -----------------------------------------
__global__ void k_detect(const void* ei, int e, int n) {
    if (blockIdx.x != 0 || threadIdx.x != 0) return;
    const long long* p = (const long long*)ei;
    int ok = 1;
    int step = e / 64;
    if (step < 1) step = 1;
    for (int k = 0; k < 64; k++) {
        long long v = p[(size_t)k * step];
        if (v < 0 || v >= n) { ok = 0; break; }
    }
    g_is64 = ok;
}

// ---- K0: zero degree ------------------------------------------------------
__global__ void k_zero_deg(int n) {
    int i = blockIdx.x * blockDim.x + threadIdx.x;
    if (i < n) g_deg[i] = 0;
}

// ---- K1: in-degree count (dst half only) ----------------------------------
__global__ void k_degree(const void* __restrict__ ei, int e, int n) {
    int i = blockIdx.x * blockDim.x + threadIdx.x;
    if (i >= e) return;
    int d;
    if (g_is64) {
        long long dv = __ldg(&((const long long*)ei)[(size_t)e + i]);
        if (dv < 0 || dv >= n) return;
        d = (int)dv;
    } else {
        d = __ldg(&((const int*)ei)[(size_t)e + i]);
        if ((unsigned)d >= (unsigned)n) return;
    }
    atomicAdd(&g_deg[d], 1);
}

// ---- K2: dinv, scaled x (padded float4), a1 init --------------------------
__global__ void k_node1(const float* __restrict__ x, int n) {
    int i = blockIdx.x * blockDim.x + threadIdx.x;
    if (i >= n) return;
    float di = rsqrtf((float)(g_deg[i] + 1));
    g_dinv[i] = di;
    float4 v = make_float4(di * __ldg(&x[3*i+0]),
                           di * __ldg(&x[3*i+1]),
                           di * __ldg(&x[3*i+2]), 0.0f);
    ((float4*)g_x4)[i] = v;
    ((float4*)g_a1)[i] = v;   // accumulator init = self-loop term
}

// ---- K3: layer-1 edge scatter (1 gather + 1 red per edge) -----------------
__global__ void k_edge1(const void* __restrict__ ei, int e, int n) {
    int i = blockIdx.x * blockDim.x + threadIdx.x;
    if (i >= e) return;
    int is64 = g_is64;
    int s, d;
    if (!load_edge(ei, e, i, n, is64, s, d)) return;
    float4 v = __ldg(&((const float4*)g_x4)[s]);
    red_add_v4(g_a1 + (size_t)d * 4, v);
}

// ---- K4: finish layer 1 (3->16 GEMM, ReLU), build scaled hW2 --------------
__global__ void k_node2(const float* __restrict__ W1,
                        const float* __restrict__ b1,
                        const float* __restrict__ W2, int n) {
    int i = blockIdx.x * blockDim.x + threadIdx.x;
    if (i >= n) return;
    float di = g_dinv[i];
    float4 a = ((const float4*)g_a1)[i];
    float a0 = di * a.x, a1v = di * a.y, a2 = di * a.z;
    float h[F1];
    #pragma unroll
    for (int j = 0; j < F1; j++)
        h[j] = fmaxf(a0 * __ldg(&W1[j]) + a1v * __ldg(&W1[F1 + j])
                   + a2 * __ldg(&W1[2*F1 + j]) + __ldg(&b1[j]), 0.0f);
    size_t ob = (size_t)i * F2P;
    float v[F2P];
    #pragma unroll
    for (int j = 0; j < F2; j++) {
        float acc = 0.0f;
        #pragma unroll
        for (int k = 0; k < F1; k++)
            acc += h[k] * __ldg(&W2[k * F2 + j]);
        v[j] = di * acc;
    }
    v[F2] = 0.0f;
    float4 p0 = make_float4(v[0], v[1], v[2], v[3]);
    float4 p1 = make_float4(v[4], v[5], v[6], v[7]);
    ((float4*)(g_hw2  + ob))[0] = p0;
    ((float4*)(g_hw2  + ob))[1] = p1;
    ((float4*)(g_acc2 + ob))[0] = p0;   // accumulator init = self-loop term
    ((float4*)(g_acc2 + ob))[1] = p1;
}

// ---- K5: layer-2 edge scatter ---------------------------------------------
__global__ void k_edge2(const void* __restrict__ ei, int e, int n) {
    int i = blockIdx.x * blockDim.x + threadIdx.x;
    if (i >= e) return;
    int is64 = g_is64;
    int s, d;
    if (!load_edge(ei, e, i, n, is64, s, d)) return;
    const float4* xs = (const float4*)(g_hw2 + (size_t)s * F2P);
    float*        ad = g_acc2 + (size_t)d * F2P;
    red_add_v4(ad + 0, __ldg(&xs[0]));
    red_add_v4(ad + 4, __ldg(&xs[1]));
}

// ---- K6: apply dinv, +b2, log_softmax -------------------------------------
__global__ void k_out(const float* __restrict__ b2, float* __restrict__ out, int n) {
    int i = blockIdx.x * blockDim.x + threadIdx.x;
    if (i >= n) return;
    float di = g_dinv[i];
    size_t ob = (size_t)i * F2P;
    float v[F2];
    float m = -1e30f;
    #pragma unroll
    for (int j = 0; j < F2; j++) {
        v[j] = di * g_acc2[ob + j] + __ldg(&b2[j]);
        m = fmaxf(m, v[j]);
    }
    float sum = 0.0f;
    #pragma unroll
    for (int j = 0; j < F2; j++) sum += __expf(v[j] - m);
    float lse = m + __logf(sum);
    #pragma unroll
    for (int j = 0; j < F2; j++) out[(size_t)i * F2 + j] = v[j] - lse;
}

// ---------------------------------------------------------------------------
extern "C" void kernel_launch(void* const* d_in, const int* in_sizes, int n_in,
                              void* d_out, int out_size) {
    const float* x  = (const float*)d_in[0];
    const void*  ei = d_in[1];                 // [2, E] int64 OR int32 (detected)
    const float* W1 = (const float*)d_in[2];
    const float* b1 = (const float*)d_in[3];
    const float* W2 = (const float*)d_in[4];
    const float* b2 = (const float*)d_in[5];
    float*       out = (float*)d_out;

    const int n = in_sizes[0] / 3;
    const int e = in_sizes[1] / 2;

    const int BT = 256;
    const int nb_n = (n + BT - 1) / BT;
    const int nb_e = (e + BT - 1) / BT;

    k_detect  <<<1, 32>>>(ei, e, n);
    k_zero_deg<<<nb_n, BT>>>(n);
    k_degree  <<<nb_e, BT>>>(ei, e, n);
    k_node1   <<<nb_n, BT>>>(x, n);
    k_edge1   <<<nb_e, BT>>>(ei, e, n);
    k_node2   <<<nb_n, BT>>>(W1, b1, W2, n);
    k_edge2   <<<nb_e, BT>>>(ei, e, n);
    k_out     <<<nb_n, BT>>>(b2, out, n);
}

// round 9
// speedup vs baseline: 2.3196x; 1.0178x over previous
#include <cuda_runtime.h>
#include <cuda_bf16.h>
#include <cstdint>

// ---------------------------------------------------------------------------
// GCN 2-layer forward. N=500000, E=16e6.
// Rank-3 trick: layer-1 aggregation on raw scaled features (float4):
//   g_x4[i]  = dinv_i * (x_i, 0)
//   a1[d]   += g_x4[s]; init a1[i] = g_x4[i]  (self loop)
//   h[i]     = relu( (dinv_i * a1[i]) @ W1 + b1 )
//   g_hw2[i] = dinv_i * (h[i] @ W2)     [8 floats, 7 used]
//   acc2[d] += g_hw2[s]; init acc2[i] = g_hw2[i]
//   out      = log_softmax(dinv_i*acc2[i] + b2)
// Edge kernels: 2 edges/thread, 16B vector index loads (streaming hint),
// pure gather+reduce. No scratch repack arrays (crash-correlated).
// ---------------------------------------------------------------------------

#define NMAX 500000
#define F1   16
#define F2   7
#define F2P  8

__device__ __align__(16) int   g_deg [NMAX];
__device__ __align__(16) float g_dinv[NMAX];
__device__ __align__(16) float g_x4  [(size_t)NMAX * 4];
__device__ __align__(16) float g_a1  [(size_t)NMAX * 4];
__device__ __align__(16) float g_hw2 [(size_t)NMAX * F2P];
__device__ __align__(16) float g_acc2[(size_t)NMAX * F2P];
__device__ int g_is64;

__device__ __forceinline__ void red_add_v4(float* addr, float4 v) {
    asm volatile("red.global.add.v4.f32 [%0], {%1, %2, %3, %4};"
                 :: "l"(addr), "f"(v.x), "f"(v.y), "f"(v.z), "f"(v.w)
                 : "memory");
}

// streaming 16B load of two int64 indices
__device__ __forceinline__ longlong2 ldcs_ll2(const long long* p) {
    longlong2 r;
    asm volatile("ld.global.cs.v2.s64 {%0, %1}, [%2];"
                 : "=l"(r.x), "=l"(r.y) : "l"(p));
    return r;
}

// ---- K-1: detect edge_index dtype -----------------------------------------
__global__ void k_detect(const void* ei, int e, int n) {
    if (blockIdx.x != 0 || threadIdx.x != 0) return;
    const long long* p = (const long long*)ei;
    int ok = 1;
    int step = e / 64;
    if (step < 1) step = 1;
    for (int k = 0; k < 64; k++) {
        long long v = p[(size_t)k * step];
        if (v < 0 || v >= n) { ok = 0; break; }
    }
    g_is64 = ok;
}

// ---- K0: zero degree ------------------------------------------------------
__global__ void k_zero_deg(int n) {
    int i = blockIdx.x * blockDim.x + threadIdx.x;
    if (i < n) g_deg[i] = 0;
}

// ---- K1: in-degree count (dst half only, 2 edges/thread) ------------------
__global__ void k_degree(const void* __restrict__ ei, int e, int n) {
    int t = blockIdx.x * blockDim.x + threadIdx.x;
    int i = t * 2;
    if (i >= e) return;
    if (g_is64) {
        const long long* dstp = (const long long*)ei + e;
        if (i + 1 < e) {
            longlong2 dv = ldcs_ll2(dstp + i);
            if (dv.x >= 0 && dv.x < n) atomicAdd(&g_deg[(int)dv.x], 1);
            if (dv.y >= 0 && dv.y < n) atomicAdd(&g_deg[(int)dv.y], 1);
        } else {
            long long dv = __ldg(dstp + i);
            if (dv >= 0 && dv < n) atomicAdd(&g_deg[(int)dv], 1);
        }
    } else {
        const int* dstp = (const int*)ei + e;
        for (int k = 0; k < 2 && i + k < e; k++) {
            int d = __ldg(dstp + i + k);
            if ((unsigned)d < (unsigned)n) atomicAdd(&g_deg[d], 1);
        }
    }
}

// ---- K2: dinv, scaled x (padded float4), a1 init --------------------------
__global__ void k_node1(const float* __restrict__ x, int n) {
    int i = blockIdx.x * blockDim.x + threadIdx.x;
    if (i >= n) return;
    float di = rsqrtf((float)(g_deg[i] + 1));
    g_dinv[i] = di;
    float4 v = make_float4(di * __ldg(&x[3*i+0]),
                           di * __ldg(&x[3*i+1]),
                           di * __ldg(&x[3*i+2]), 0.0f);
    ((float4*)g_x4)[i] = v;
    ((float4*)g_a1)[i] = v;   // accumulator init = self-loop term
}

// ---- K3: layer-1 edge scatter (2 edges/thread) ----------------------------
__global__ void k_edge1(const void* __restrict__ ei, int e, int n) {
    int t = blockIdx.x * blockDim.x + threadIdx.x;
    int i = t * 2;
    if (i >= e) return;
    if (g_is64) {
        const long long* srcp = (const long long*)ei;
        const long long* dstp = srcp + e;
        if (i + 1 < e) {
            longlong2 sv = ldcs_ll2(srcp + i);
            longlong2 dv = ldcs_ll2(dstp + i);
            bool ok0 = (sv.x >= 0 && sv.x < n && dv.x >= 0 && dv.x < n);
            bool ok1 = (sv.y >= 0 && sv.y < n && dv.y >= 0 && dv.y < n);
            if (ok0 && ok1) {
                float4 v0 = __ldg(&((const float4*)g_x4)[(int)sv.x]);
                float4 v1 = __ldg(&((const float4*)g_x4)[(int)sv.y]);
                red_add_v4(g_a1 + (size_t)(int)dv.x * 4, v0);
                red_add_v4(g_a1 + (size_t)(int)dv.y * 4, v1);
            } else {
                if (ok0) red_add_v4(g_a1 + (size_t)(int)dv.x * 4,
                                    __ldg(&((const float4*)g_x4)[(int)sv.x]));
                if (ok1) red_add_v4(g_a1 + (size_t)(int)dv.y * 4,
                                    __ldg(&((const float4*)g_x4)[(int)sv.y]));
            }
        } else {
            long long sv = __ldg(srcp + i), dv = __ldg(dstp + i);
            if (sv >= 0 && sv < n && dv >= 0 && dv < n)
                red_add_v4(g_a1 + (size_t)(int)dv * 4,
                           __ldg(&((const float4*)g_x4)[(int)sv]));
        }
    } else {
        const int* srcp = (const int*)ei;
        const int* dstp = srcp + e;
        for (int k = 0; k < 2 && i + k < e; k++) {
            int s = __ldg(srcp + i + k), d = __ldg(dstp + i + k);
            if ((unsigned)s < (unsigned)n && (unsigned)d < (unsigned)n)
                red_add_v4(g_a1 + (size_t)d * 4, __ldg(&((const float4*)g_x4)[s]));
        }
    }
}

// ---- K4: finish layer 1 (3->16 GEMM, ReLU), build scaled hW2 --------------
__global__ void k_node2(const float* __restrict__ W1,
                        const float* __restrict__ b1,
                        const float* __restrict__ W2, int n) {
    int i = blockIdx.x * blockDim.x + threadIdx.x;
    if (i >= n) return;
    float di = g_dinv[i];
    float4 a = ((const float4*)g_a1)[i];
    float a0 = di * a.x, a1v = di * a.y, a2 = di * a.z;
    float h[F1];
    #pragma unroll
    for (int j = 0; j < F1; j++)
        h[j] = fmaxf(a0 * __ldg(&W1[j]) + a1v * __ldg(&W1[F1 + j])
                   + a2 * __ldg(&W1[2*F1 + j]) + __ldg(&b1[j]), 0.0f);
    size_t ob = (size_t)i * F2P;
    float v[F2P];
    #pragma unroll
    for (int j = 0; j < F2; j++) {
        float acc = 0.0f;
        #pragma unroll
        for (int k = 0; k < F1; k++)
            acc += h[k] * __ldg(&W2[k * F2 + j]);
        v[j] = di * acc;
    }
    v[F2] = 0.0f;
    float4 p0 = make_float4(v[0], v[1], v[2], v[3]);
    float4 p1 = make_float4(v[4], v[5], v[6], v[7]);
    ((float4*)(g_hw2  + ob))[0] = p0;
    ((float4*)(g_hw2  + ob))[1] = p1;
    ((float4*)(g_acc2 + ob))[0] = p0;   // accumulator init = self-loop term
    ((float4*)(g_acc2 + ob))[1] = p1;
}

// ---- K5: layer-2 edge scatter (2 edges/thread) ----------------------------
__global__ void k_edge2(const void* __restrict__ ei, int e, int n) {
    int t = blockIdx.x * blockDim.x + threadIdx.x;
    int i = t * 2;
    if (i >= e) return;
    if (g_is64) {
        const long long* srcp = (const long long*)ei;
        const long long* dstp = srcp + e;
        if (i + 1 < e) {
            longlong2 sv = ldcs_ll2(srcp + i);
            longlong2 dv = ldcs_ll2(dstp + i);
            if (sv.x >= 0 && sv.x < n && dv.x >= 0 && dv.x < n) {
                const float4* xs = (const float4*)(g_hw2 + (size_t)(int)sv.x * F2P);
                float* ad = g_acc2 + (size_t)(int)dv.x * F2P;
                red_add_v4(ad + 0, __ldg(&xs[0]));
                red_add_v4(ad + 4, __ldg(&xs[1]));
            }
            if (sv.y >= 0 && sv.y < n && dv.y >= 0 && dv.y < n) {
                const float4* xs = (const float4*)(g_hw2 + (size_t)(int)sv.y * F2P);
                float* ad = g_acc2 + (size_t)(int)dv.y * F2P;
                red_add_v4(ad + 0, __ldg(&xs[0]));
                red_add_v4(ad + 4, __ldg(&xs[1]));
            }
        } else {
            long long sv = __ldg(srcp + i), dv = __ldg(dstp + i);
            if (sv >= 0 && sv < n && dv >= 0 && dv < n) {
                const float4* xs = (const float4*)(g_hw2 + (size_t)(int)sv * F2P);
                float* ad = g_acc2 + (size_t)(int)dv * F2P;
                red_add_v4(ad + 0, __ldg(&xs[0]));
                red_add_v4(ad + 4, __ldg(&xs[1]));
            }
        }
    } else {
        const int* srcp = (const int*)ei;
        const int* dstp = srcp + e;
        for (int k = 0; k < 2 && i + k < e; k++) {
            int s = __ldg(srcp + i + k), d = __ldg(dstp + i + k);
            if ((unsigned)s < (unsigned)n && (unsigned)d < (unsigned)n) {
                const float4* xs = (const float4*)(g_hw2 + (size_t)s * F2P);
                float* ad = g_acc2 + (size_t)d * F2P;
                red_add_v4(ad + 0, __ldg(&xs[0]));
                red_add_v4(ad + 4, __ldg(&xs[1]));
            }
        }
    }
}

// ---- K6: apply dinv, +b2, log_softmax -------------------------------------
__global__ void k_out(const float* __restrict__ b2, float* __restrict__ out, int n) {
    int i = blockIdx.x * blockDim.x + threadIdx.x;
    if (i >= n) return;
    float di = g_dinv[i];
    size_t ob = (size_t)i * F2P;
    float v[F2];
    float m = -1e30f;
    #pragma unroll
    for (int j = 0; j < F2; j++) {
        v[j] = di * g_acc2[ob + j] + __ldg(&b2[j]);
        m = fmaxf(m, v[j]);
    }
    float sum = 0.0f;
    #pragma unroll
    for (int j = 0; j < F2; j++) sum += __expf(v[j] - m);
    float lse = m + __logf(sum);
    #pragma unroll
    for (int j = 0; j < F2; j++) out[(size_t)i * F2 + j] = v[j] - lse;
}

// ---------------------------------------------------------------------------
extern "C" void kernel_launch(void* const* d_in, const int* in_sizes, int n_in,
                              void* d_out, int out_size) {
    const float* x  = (const float*)d_in[0];
    const void*  ei = d_in[1];                 // [2, E] int64 OR int32 (detected)
    const float* W1 = (const float*)d_in[2];
    const float* b1 = (const float*)d_in[3];
    const float* W2 = (const float*)d_in[4];
    const float* b2 = (const float*)d_in[5];
    float*       out = (float*)d_out;

    const int n = in_sizes[0] / 3;
    const int e = in_sizes[1] / 2;

    const int BT = 256;
    const int nb_n  = (n + BT - 1) / BT;
    const int nb_e2 = (e / 2 + BT) / BT;   // 2 edges per thread

    k_detect  <<<1, 32>>>(ei, e, n);
    k_zero_deg<<<nb_n,  BT>>>(n);
    k_degree  <<<nb_e2, BT>>>(ei, e, n);
    k_node1   <<<nb_n,  BT>>>(x, n);
    k_edge1   <<<nb_e2, BT>>>(ei, e, n);
    k_node2   <<<nb_n,  BT>>>(W1, b1, W2, n);
    k_edge2   <<<nb_e2, BT>>>(ei, e, n);
    k_out     <<<nb_n,  BT>>>(b2, out, n);
}